// round 13
// baseline (speedup 1.0000x reference)
#include <cuda_runtime.h>
#include <math.h>
#include <stdint.h>

// Problem constants (fixed by the dataset)
#define Nn   10000
#define Ee   160000
#define E2e  320000

// ---------------- scratch (device globals; no allocs allowed) ----------------
__device__ float g_lg_ni[Ee * 256];
__device__ float g_lg_nj[Ee * 256];
__device__ float g_gni  [Nn * 256];
__device__ float g_gnj  [Nn * 256];
__device__ float g_q    [Nn * 256];
__device__ float g_m1   [Ee * 256];
__device__ float g_h1   [Ee * 256];
__device__ float g_h2   [Ee * 256];
__device__ float g_slg  [E2e * 4];
__device__ float g_maxlg[Ee * 4];
__device__ float g_denlg[Ee * 4];
__device__ float g_sg   [Ee * 4];
__device__ float g_maxg [Nn * 4];
__device__ float g_deng [Nn * 4];
// CSR of lg_dst
__device__ int   g_rcnt  [Ee];
__device__ int   g_fill  [Ee];
__device__ int   g_rowptr[Ee + 1];
__device__ int   g_eidx  [E2e];
__device__ int   g_bsum  [640];
__device__ int   g_boff  [640];

__device__ __forceinline__ float lrelu(float x) { return x > 0.f ? x : 0.01f * x; }

__device__ __forceinline__ void atomicMaxF(float* addr, float val) {
    int* ia = (int*)addr;
    int old = __float_as_int(*addr);
    while (__int_as_float(old) < val) {
        int assumed = old;
        old = atomicCAS(ia, assumed, __float_as_int(val));
        if (old == assumed) break;
    }
}

__device__ __forceinline__ uint32_t cvt_tf32(float f) {
    uint32_t r;
    asm("cvt.rna.tf32.f32 %0, %1;" : "=r"(r) : "f"(f));
    return r;
}

// ========== tf32 mma.sync GEMM core ==========
// A smem: [k][m'] with m' = (m&7)*2 + ((m>>3)&1) + ((m>>4)<<4) -> A frag = 2x LDS.64.
// W smem: [k][n] plain (R7 layout). Stride 136 both.
#define SST  136
#define BUFU (16 * SST)

__device__ __forceinline__ void gemm_core(
    const float* __restrict__ A, const float* __restrict__ Wr,
    int M, int K,
    uint32_t* As, uint32_t* Ws,
    int arow, int r_st, int kqh, int mb, int nb, int gid, int tg,
    float (&acc)[2][8][4])
{
    const float4 z4 = make_float4(0.f, 0.f, 0.f, 0.f);
    float4 pa[2], pw[2];
    const int mp = ((r_st & 7) * 2) + ((r_st >> 3) & 1) + ((r_st >> 4) << 4);

#pragma unroll
    for (int i = 0; i < 2; i++) {
        int kb = (kqh + 2 * i) * 4;
        pa[i] = (arow < M) ? *(const float4*)(A + (size_t)arow * K + kb) : z4;
        pw[i] = *(const float4*)(Wr + kb);
    }
#pragma unroll
    for (int i = 0; i < 2; i++) {
        int kb = (kqh + 2 * i) * 4;
        As[(kb + 0) * SST + mp] = cvt_tf32(pa[i].x);
        As[(kb + 1) * SST + mp] = cvt_tf32(pa[i].y);
        As[(kb + 2) * SST + mp] = cvt_tf32(pa[i].z);
        As[(kb + 3) * SST + mp] = cvt_tf32(pa[i].w);
        Ws[(kb + 0) * SST + r_st] = cvt_tf32(pw[i].x);
        Ws[(kb + 1) * SST + r_st] = cvt_tf32(pw[i].y);
        Ws[(kb + 2) * SST + r_st] = cvt_tf32(pw[i].z);
        Ws[(kb + 3) * SST + r_st] = cvt_tf32(pw[i].w);
    }
    __syncthreads();

    const int nk = K >> 4;
    for (int t = 0; t < nk; t++) {
        const int cur = t & 1;
        if (t + 1 < nk) {
            const int k0 = (t + 1) << 4;
#pragma unroll
            for (int i = 0; i < 2; i++) {
                int kb = k0 + (kqh + 2 * i) * 4;
                pa[i] = (arow < M) ? *(const float4*)(A + (size_t)arow * K + kb) : z4;
                pw[i] = *(const float4*)(Wr + kb);
            }
        }
        const uint32_t* Ab = As + cur * BUFU;
        const uint32_t* Wb = Ws + cur * BUFU;
#pragma unroll
        for (int kk = 0; kk < 16; kk += 8) {
            uint32_t af[2][4], bf[8][2];
#pragma unroll
            for (int mt = 0; mt < 2; mt++) {
                int mt16 = (mb >> 4) + mt;           // 16-row tile index
                uint2 v0 = *(const uint2*)(Ab + (kk + tg)     * SST + mt16 * 16 + 2 * gid);
                uint2 v1 = *(const uint2*)(Ab + (kk + tg + 4) * SST + mt16 * 16 + 2 * gid);
                af[mt][0] = v0.x; af[mt][1] = v0.y;
                af[mt][2] = v1.x; af[mt][3] = v1.y;
            }
#pragma unroll
            for (int nt = 0; nt < 8; nt++) {
                int n = nb + nt * 8 + gid;
                bf[nt][0] = Wb[(kk + tg)     * SST + n];
                bf[nt][1] = Wb[(kk + tg + 4) * SST + n];
            }
#pragma unroll
            for (int mt = 0; mt < 2; mt++)
#pragma unroll
                for (int nt = 0; nt < 8; nt++)
                    asm volatile(
                        "mma.sync.aligned.m16n8k8.row.col.f32.tf32.tf32.f32 "
                        "{%0,%1,%2,%3}, {%4,%5,%6,%7}, {%8,%9}, {%0,%1,%2,%3};"
                        : "+f"(acc[mt][nt][0]), "+f"(acc[mt][nt][1]),
                          "+f"(acc[mt][nt][2]), "+f"(acc[mt][nt][3])
                        : "r"(af[mt][0]), "r"(af[mt][1]), "r"(af[mt][2]), "r"(af[mt][3]),
                          "r"(bf[nt][0]), "r"(bf[nt][1]));
        }
        if (t + 1 < nk) {
            const int nxt = cur ^ 1;
            uint32_t* An = As + nxt * BUFU;
            uint32_t* Wn = Ws + nxt * BUFU;
#pragma unroll
            for (int i = 0; i < 2; i++) {
                int kb = (kqh + 2 * i) * 4;
                An[(kb + 0) * SST + mp] = cvt_tf32(pa[i].x);
                An[(kb + 1) * SST + mp] = cvt_tf32(pa[i].y);
                An[(kb + 2) * SST + mp] = cvt_tf32(pa[i].z);
                An[(kb + 3) * SST + mp] = cvt_tf32(pa[i].w);
                Wn[(kb + 0) * SST + r_st] = cvt_tf32(pw[i].x);
                Wn[(kb + 1) * SST + r_st] = cvt_tf32(pw[i].y);
                Wn[(kb + 2) * SST + r_st] = cvt_tf32(pw[i].z);
                Wn[(kb + 3) * SST + r_st] = cvt_tf32(pw[i].w);
            }
            __syncthreads();
        }
    }
}

#define GEMM_PREAMBLE                                        \
    __shared__ uint32_t As[2 * BUFU];                        \
    __shared__ uint32_t Ws[2 * BUFU];                        \
    const int tid  = threadIdx.x;                            \
    const int lane = tid & 31;                               \
    const int warp = tid >> 5;                               \
    const int gid  = lane >> 2;                              \
    const int tg   = lane & 3;                               \
    const int mb   = (warp & 3) * 32;                        \
    const int nb   = (warp >> 2) * 64;                       \
    const int bm   = blockIdx.y * 128;                       \
    const int r_st = tid & 127;                              \
    const int kqh  = tid >> 7;                               \
    const int arow = bm + r_st;                              \
    float acc[2][8][4];                                      \
    _Pragma("unroll")                                        \
    for (int a_ = 0; a_ < 2; a_++)                           \
        _Pragma("unroll")                                    \
        for (int b_ = 0; b_ < 8; b_++)                       \
            _Pragma("unroll")                                \
            for (int c_ = 0; c_ < 4; c_++) acc[a_][b_][c_] = 0.f;

// Standard GEMM: C[M,256] = A[M,K] @ W^T (+bias); W row stride = wstride.
__global__ __launch_bounds__(256) void mmagemm(const float* __restrict__ A,
                                               const float* __restrict__ W, int wstride,
                                               const float* __restrict__ bias,
                                               float* __restrict__ C,
                                               int M, int K)
{
    GEMM_PREAMBLE
    const int bn = blockIdx.x * 128;
    const float* Wr = W + (size_t)(bn + r_st) * wstride;
    gemm_core(A, Wr, M, K, As, Ws, arow, r_st, kqh, mb, nb, gid, tg, acc);

#pragma unroll
    for (int mt = 0; mt < 2; mt++) {
        int row0 = bm + mb + mt * 16 + gid;
#pragma unroll
        for (int nt = 0; nt < 8; nt++) {
            int col = bn + nb + nt * 8 + tg * 2;
            float bx = 0.f, by = 0.f;
            if (bias) { bx = bias[col]; by = bias[col + 1]; }
            if (row0 < M)
                *(float2*)(C + (size_t)row0 * 256 + col) =
                    make_float2(acc[mt][nt][0] + bx, acc[mt][nt][1] + by);
            if (row0 + 8 < M)
                *(float2*)(C + (size_t)(row0 + 8) * 256 + col) =
                    make_float2(acc[mt][nt][2] + bx, acc[mt][nt][3] + by);
        }
    }
}

// Dual-output GEMM: reads A once, computes C1 = A@W1^T and C2 = A@W2^T.
__global__ __launch_bounds__(256) void mmagemm2(const float* __restrict__ A,
                                                const float* __restrict__ W1,
                                                const float* __restrict__ W2,
                                                float* __restrict__ C1,
                                                float* __restrict__ C2,
                                                int M, int K)
{
    GEMM_PREAMBLE
    const int bnf = blockIdx.x * 128;
    const float* W = (bnf < 256) ? W1 : W2;
    float* C = (bnf < 256) ? C1 : C2;
    const int bn = bnf & 255;
    const float* Wr = W + (size_t)(bn + r_st) * K;
    gemm_core(A, Wr, M, K, As, Ws, arow, r_st, kqh, mb, nb, gid, tg, acc);

#pragma unroll
    for (int mt = 0; mt < 2; mt++) {
        int row0 = bm + mb + mt * 16 + gid;
#pragma unroll
        for (int nt = 0; nt < 8; nt++) {
            int col = bn + nb + nt * 8 + tg * 2;
            if (row0 < M)
                *(float2*)(C + (size_t)row0 * 256 + col) =
                    make_float2(acc[mt][nt][0], acc[mt][nt][1]);
            if (row0 + 8 < M)
                *(float2*)(C + (size_t)(row0 + 8) * 256 + col) =
                    make_float2(acc[mt][nt][2], acc[mt][nt][3]);
        }
    }
}

// GEMM + node-gather epilogue: C[r,c] = acc + bias[c] + q[src[r],c] + q[dst[r],c].
__global__ __launch_bounds__(256) void mmagemm_nodeadd(const float* __restrict__ A,
                                                       const float* __restrict__ W, int wstride,
                                                       const float* __restrict__ bias,
                                                       const float* __restrict__ q,
                                                       const int* __restrict__ srcIdx,
                                                       const int* __restrict__ dstIdx,
                                                       float* __restrict__ C,
                                                       int M, int K)
{
    GEMM_PREAMBLE
    const int bn = blockIdx.x * 128;
    const float* Wr = W + (size_t)(bn + r_st) * wstride;
    gemm_core(A, Wr, M, K, As, Ws, arow, r_st, kqh, mb, nb, gid, tg, acc);

#pragma unroll
    for (int mt = 0; mt < 2; mt++) {
        int rbase = bm + mb + mt * 16 + gid;
#pragma unroll
        for (int half = 0; half < 2; half++) {
            int rr = rbase + half * 8;
            const float* qs = q + (size_t)srcIdx[rr] * 256;
            const float* qd = q + (size_t)dstIdx[rr] * 256;
#pragma unroll
            for (int nt = 0; nt < 8; nt++) {
                int col = bn + nb + nt * 8 + tg * 2;
                float v0 = acc[mt][nt][half * 2 + 0] + bias[col]     + qs[col]     + qd[col];
                float v1 = acc[mt][nt][half * 2 + 1] + bias[col + 1] + qs[col + 1] + qd[col + 1];
                *(float2*)(C + (size_t)rr * 256 + col) = make_float2(v0, v1);
            }
        }
    }
}

// GEMM + fused attention-score epilogue (P never stored). Requires M%128==0.
__global__ __launch_bounds__(256) void mmagemm_score(const float* __restrict__ A,
                                                     const float* __restrict__ W,
                                                     const float* __restrict__ ni,
                                                     const float* __restrict__ nj,
                                                     const int* __restrict__ srcIdx,
                                                     const int* __restrict__ dstIdx,
                                                     const float* __restrict__ attn,
                                                     const float* __restrict__ bias,
                                                     float* __restrict__ scoreOut,
                                                     float* __restrict__ maxOut,
                                                     int M, int K)
{
    GEMM_PREAMBLE
    const int bn = blockIdx.x * 128;
    const float* Wr = W + (size_t)(bn + r_st) * K;
    gemm_core(A, Wr, M, K, As, Ws, arow, r_st, kqh, mb, nb, gid, tg, acc);

    const int h = (bn + nb) >> 6;
#pragma unroll
    for (int mt = 0; mt < 2; mt++) {
        int rbase = bm + mb + mt * 16 + gid;
#pragma unroll
        for (int half = 0; half < 2; half++) {
            int rr = rbase + half * 8;
            int s_ = srcIdx[rr];
            int d_ = dstIdx[rr];
            const float* nip = ni + (size_t)s_ * 256;
            const float* njp = nj + (size_t)d_ * 256;
            float part = 0.f;
#pragma unroll
            for (int nt = 0; nt < 8; nt++) {
                int col = bn + nb + nt * 8 + tg * 2;
                float p0 = acc[mt][nt][half * 2 + 0];
                float p1 = acc[mt][nt][half * 2 + 1];
                part += lrelu(nip[col]     + njp[col]     + p0 + bias[col])     * attn[col];
                part += lrelu(nip[col + 1] + njp[col + 1] + p1 + bias[col + 1]) * attn[col + 1];
            }
            part += __shfl_xor_sync(0xffffffffu, part, 1);
            part += __shfl_xor_sync(0xffffffffu, part, 2);
            if (tg == 0) {
                scoreOut[(size_t)rr * 4 + h] = part;
                if (maxOut) atomicMaxF(&maxOut[(size_t)d_ * 4 + h], part);
            }
        }
    }
}

// ---------------- CSR build (3-stage scan) ----------------
__global__ void hist_kernel(const int* __restrict__ lgdst) {
    int e2 = blockIdx.x * blockDim.x + threadIdx.x;
    if (e2 < E2e) atomicAdd(&g_rcnt[lgdst[e2]], 1);
}

// per-256-block exclusive scan of g_rcnt -> g_rowptr (in-block), block totals -> g_bsum
__global__ __launch_bounds__(256) void scan1_kernel() {
    __shared__ int sh[256];
    int j = blockIdx.x * 256 + threadIdx.x;
    int t = threadIdx.x;
    int v = (j < Ee) ? g_rcnt[j] : 0;
    sh[t] = v;
    __syncthreads();
    // inclusive scan
    for (int off = 1; off < 256; off <<= 1) {
        int u = (t >= off) ? sh[t - off] : 0;
        __syncthreads();
        sh[t] += u;
        __syncthreads();
    }
    if (j < Ee) g_rowptr[j] = sh[t] - v;   // exclusive within block
    if (t == 255) g_bsum[blockIdx.x] = sh[255];
}

__global__ __launch_bounds__(1024) void scan2_kernel(int nblocks) {
    __shared__ int sh[1024];
    int t = threadIdx.x;
    int v = (t < nblocks) ? g_bsum[t] : 0;
    sh[t] = v;
    __syncthreads();
    for (int off = 1; off < 1024; off <<= 1) {
        int u = (t >= off) ? sh[t - off] : 0;
        __syncthreads();
        sh[t] += u;
        __syncthreads();
    }
    if (t < nblocks) g_boff[t] = sh[t] - v;   // exclusive
}

__global__ void scan3_kernel() {
    int j = blockIdx.x * 256 + threadIdx.x;
    if (j < Ee) g_rowptr[j] += g_boff[blockIdx.x];
    if (j == 0) g_rowptr[Ee] = E2e;
}

__global__ void scatter_csr_kernel(const int* __restrict__ lgdst) {
    int e2 = blockIdx.x * blockDim.x + threadIdx.x;
    if (e2 >= E2e) return;
    int d = lgdst[e2];
    int p = g_rowptr[d] + atomicAdd(&g_fill[d], 1);
    g_eidx[p] = e2;
}

// ---------------- small kernels ----------------
__global__ void fill_kernel(float* p, float v, int n) {
    int t = blockIdx.x * blockDim.x + threadIdx.x;
    if (t < n) p[t] = v;
}

__global__ __launch_bounds__(128) void agg_m1_kernel(const float* __restrict__ m_feats,
                                                     const float* __restrict__ x_feats) {
    int e = blockIdx.x;
    int c = threadIdx.x;
    int r0 = g_rowptr[e], r1 = g_rowptr[e + 1];
    float s = 0.f;
    for (int i = r0; i < r1; i++)
        s += x_feats[(size_t)g_eidx[i] * 128 + c];
    float inv = 1.f / fmaxf((float)(r1 - r0), 1.f);
    g_m1[(size_t)e * 256 + c]       = m_feats[(size_t)e * 128 + c];
    g_m1[(size_t)e * 256 + 128 + c] = s * inv;
}

// CSR segmented softmax stats per (dst l-node, head)
__global__ void lgsoftmax_kernel() {
    int t = blockIdx.x * blockDim.x + threadIdx.x;
    if (t >= Ee * 4) return;
    int e = t >> 2, h = t & 3;
    int r0 = g_rowptr[e], r1 = g_rowptr[e + 1];
    float m = -INFINITY;
    for (int i = r0; i < r1; i++)
        m = fmaxf(m, g_slg[(size_t)g_eidx[i] * 4 + h]);
    float den = 0.f;
    for (int i = r0; i < r1; i++)
        den += expf(g_slg[(size_t)g_eidx[i] * 4 + h] - m);
    g_maxlg[t] = m;
    g_denlg[t] = (r1 > r0) ? den : 1.f;
}

__global__ void g_exp_kernel(const int* __restrict__ dst) {
    int t = blockIdx.x * blockDim.x + threadIdx.x;
    if (t >= Ee * 4) return;
    int e = t >> 2, h = t & 3;
    int d = dst[e];
    float v = expf(g_sg[t] - g_maxg[(size_t)d * 4 + h]);
    g_sg[t] = v;
    atomicAdd(&g_deng[(size_t)d * 4 + h], v);
}

// fused CSR gather of both branches + softmax normalize + lrelu head-sum epilogue
__global__ __launch_bounds__(256) void gather_final_kernel(const int* __restrict__ lgsrc,
                                                           const int* __restrict__ gdst,
                                                           float* __restrict__ out) {
    __shared__ float red[256];
    int e = blockIdx.x;
    int c = threadIdx.x;
    int h = c >> 6;
    int r0 = g_rowptr[e], r1 = g_rowptr[e + 1];
    float agh = g_sg[(size_t)e * 4 + h] / g_deng[(size_t)gdst[e] * 4 + h];
    float mx  = g_maxlg[(size_t)e * 4 + h];
    float inv = 1.f / g_denlg[(size_t)e * 4 + h];
    float a1 = 0.f, a2 = 0.f;
    for (int i = r0; i < r1; i++) {
        int e2 = g_eidx[i];
        int s = lgsrc[e2];
        float alg = expf(g_slg[(size_t)e2 * 4 + h] - mx) * inv;
        a1 += g_h1[(size_t)s * 256 + c] * alg;
        a2 += g_h2[(size_t)s * 256 + c] * agh;
    }
    red[c] = lrelu(a1) + lrelu(a2);
    __syncthreads();
    if (c < 64)
        out[(size_t)e * 64 + c] = red[c] + red[c + 64] + red[c + 128] + red[c + 192];
}

// ---------------- host launch ----------------
extern "C" void kernel_launch(void* const* d_in, const int* in_sizes, int n_in,
                              void* d_out, int out_size)
{
    const float *l_feats = (const float*)d_in[0];
    const float *m_feats = (const float*)d_in[1];
    const float *x_feats = (const float*)d_in[2];
    const float *W_lg_node, *b_lg_node, *W_lg_ni, *W_lg_fij, *W_lg_nj, *lg_attn, *bias_lg;
    const float *W_g_node, *b_g_node, *W_g_ni, *W_g_fij, *W_g_nj, *g_attn, *bias_g;
    const int *gsrc, *gdst, *lgsrc, *lgdst;

    if (in_sizes[3] == Ee) {  // setup_inputs dict order
        gsrc = (const int*)d_in[3];  gdst = (const int*)d_in[4];
        lgsrc = (const int*)d_in[5]; lgdst = (const int*)d_in[6];
        W_lg_node = (const float*)d_in[7];  b_lg_node = (const float*)d_in[8];
        W_lg_ni   = (const float*)d_in[9];  W_lg_fij  = (const float*)d_in[10];
        W_lg_nj   = (const float*)d_in[11]; lg_attn   = (const float*)d_in[12];
        bias_lg   = (const float*)d_in[13];
        W_g_node  = (const float*)d_in[14]; b_g_node  = (const float*)d_in[15];
        W_g_ni    = (const float*)d_in[16]; W_g_fij   = (const float*)d_in[17];
        W_g_nj    = (const float*)d_in[18]; g_attn    = (const float*)d_in[19];
        bias_g    = (const float*)d_in[20];
    } else {                  // reference() signature order
        W_lg_node = (const float*)d_in[3];  b_lg_node = (const float*)d_in[4];
        W_lg_ni   = (const float*)d_in[5];  W_lg_fij  = (const float*)d_in[6];
        W_lg_nj   = (const float*)d_in[7];  lg_attn   = (const float*)d_in[8];
        bias_lg   = (const float*)d_in[9];
        W_g_node  = (const float*)d_in[10]; b_g_node  = (const float*)d_in[11];
        W_g_ni    = (const float*)d_in[12]; W_g_fij   = (const float*)d_in[13];
        W_g_nj    = (const float*)d_in[14]; g_attn    = (const float*)d_in[15];
        bias_g    = (const float*)d_in[16];
        gsrc  = (const int*)d_in[17]; gdst  = (const int*)d_in[18];
        lgsrc = (const int*)d_in[19]; lgdst = (const int*)d_in[20];
    }

    float *p_lg_ni, *p_lg_nj, *p_gni, *p_gnj, *p_q;
    float *p_m1, *p_h1, *p_h2, *p_maxg, *p_deng, *p_slg, *p_sg;
    int *p_rcnt, *p_fill;
    cudaGetSymbolAddress((void**)&p_lg_ni, g_lg_ni);
    cudaGetSymbolAddress((void**)&p_lg_nj, g_lg_nj);
    cudaGetSymbolAddress((void**)&p_gni,   g_gni);
    cudaGetSymbolAddress((void**)&p_gnj,   g_gnj);
    cudaGetSymbolAddress((void**)&p_q,     g_q);
    cudaGetSymbolAddress((void**)&p_m1,    g_m1);
    cudaGetSymbolAddress((void**)&p_h1,    g_h1);
    cudaGetSymbolAddress((void**)&p_h2,    g_h2);
    cudaGetSymbolAddress((void**)&p_maxg,  g_maxg);
    cudaGetSymbolAddress((void**)&p_deng,  g_deng);
    cudaGetSymbolAddress((void**)&p_slg,   g_slg);
    cudaGetSymbolAddress((void**)&p_sg,    g_sg);
    cudaGetSymbolAddress((void**)&p_rcnt,  g_rcnt);
    cudaGetSymbolAddress((void**)&p_fill,  g_fill);

    // ---- fork: CSR + aggregation chain on side stream ----
    cudaStream_t s2;
    cudaStreamCreateWithFlags(&s2, cudaStreamNonBlocking);
    cudaEvent_t ev0, ev2;
    cudaEventCreateWithFlags(&ev0, cudaEventDisableTiming);
    cudaEventCreateWithFlags(&ev2, cudaEventDisableTiming);
    cudaEventRecord(ev0, 0);
    cudaStreamWaitEvent(s2, ev0, 0);

    const int nsb = (Ee + 255) / 256;   // 625 scan blocks
    cudaMemsetAsync(p_rcnt, 0, sizeof(int) * Ee, s2);
    cudaMemsetAsync(p_fill, 0, sizeof(int) * Ee, s2);
    hist_kernel<<<(E2e + 255) / 256, 256, 0, s2>>>(lgdst);
    scan1_kernel<<<nsb, 256, 0, s2>>>();
    scan2_kernel<<<1, 1024, 0, s2>>>(nsb);
    scan3_kernel<<<nsb, 256, 0, s2>>>();
    scatter_csr_kernel<<<(E2e + 255) / 256, 256, 0, s2>>>(lgdst);
    agg_m1_kernel<<<Ee, 128, 0, s2>>>(m_feats, x_feats);
    cudaEventRecord(ev2, s2);

    // ---- main stream: init + GEMMs ----
    cudaMemsetAsync(p_deng, 0, sizeof(float) * Nn * 4, 0);
    fill_kernel<<<(Nn * 4 + 255) / 256, 256>>>(p_maxg, -INFINITY, Nn * 4);

    dim3 blk(256);
    const int gE  = (Ee  + 127) / 128;
    const int gE2 = (E2e + 127) / 128;
    const int gN  = (Nn  + 127) / 128;
    mmagemm2<<<dim3(4, gE), blk>>>(m_feats, W_lg_ni, W_lg_nj, p_lg_ni, p_lg_nj, Ee, 128);
    mmagemm2<<<dim3(4, gN), blk>>>(l_feats, W_g_ni,  W_g_nj,  p_gni,   p_gnj,   Nn, 128);

    mmagemm_score<<<dim3(2, gE2), blk>>>(x_feats, W_lg_fij, p_lg_ni, p_lg_nj,
                                         lgsrc, lgdst, lg_attn, bias_lg,
                                         p_slg, nullptr, E2e, 128);
    mmagemm_score<<<dim3(2, gE), blk>>>(m_feats, W_g_fij, p_gni, p_gnj,
                                        gsrc, gdst, g_attn, bias_g,
                                        p_sg, p_maxg, Ee, 128);

    // h2 via q-trick
    mmagemm<<<dim3(2, gN), blk>>>(l_feats, W_g_node, 256, nullptr, p_q, Nn, 128);
    mmagemm_nodeadd<<<dim3(2, gE), blk>>>(m_feats, W_g_node + 128, 256, b_g_node,
                                          p_q, gsrc, gdst, p_h2, Ee, 128);

    // ---- join: need m1 + CSR from s2 ----
    cudaStreamWaitEvent(0, ev2, 0);

    mmagemm<<<dim3(2, gE), blk>>>(p_m1, W_lg_node, 256, b_lg_node, p_h1, Ee, 256);
    lgsoftmax_kernel<<<(Ee * 4 + 255) / 256, 256>>>();
    g_exp_kernel<<<(Ee * 4 + 255) / 256, 256>>>(gdst);

    gather_final_kernel<<<Ee, 256>>>(lgsrc, gdst, (float*)d_out);
    // Intentionally not destroying s2/ev0/ev2 here: capture is still active
    // when kernel_launch returns; destroying capture-participating resources
    // would invalidate the graph. Handles are tiny and leak a bounded number
    // of times (correctness + capture calls only).
}

// round 15
// speedup vs baseline: 1.3661x; 1.3661x over previous
#include <cuda_runtime.h>
#include <math.h>
#include <stdint.h>

// Problem constants (fixed by the dataset)
#define Nn   10000
#define Ee   160000
#define E2e  320000

// ---------------- scratch (device globals; no allocs allowed) ----------------
__device__ float g_lg_ni[Ee * 256];
__device__ float g_lg_nj[Ee * 256];
__device__ float g_gni  [Nn * 256];
__device__ float g_gnj  [Nn * 256];
__device__ float g_q    [Nn * 256];
__device__ float g_m1   [Ee * 256];
__device__ float g_h12  [(size_t)Ee * 512];   // [e][0:256)=h1, [e][256:512)=h2
__device__ float g_slg  [E2e * 4];
__device__ float g_maxlg[Ee * 4];
__device__ float g_denlg[Ee * 4];
__device__ float g_sg   [Ee * 4];
__device__ float g_maxg [Nn * 4];
__device__ float g_deng [Nn * 4];
// CSR of lg_dst
__device__ int   g_rcnt  [Ee];
__device__ int   g_fill  [Ee];
__device__ int   g_rowptr[Ee + 1];
__device__ int   g_eidx  [E2e];
__device__ int   g_bsum  [640];
__device__ int   g_boff  [640];

__device__ __forceinline__ float lrelu(float x) { return x > 0.f ? x : 0.01f * x; }

__device__ __forceinline__ void atomicMaxF(float* addr, float val) {
    int* ia = (int*)addr;
    int old = __float_as_int(*addr);
    while (__int_as_float(old) < val) {
        int assumed = old;
        old = atomicCAS(ia, assumed, __float_as_int(val));
        if (old == assumed) break;
    }
}

__device__ __forceinline__ uint32_t cvt_tf32(float f) {
    uint32_t r;
    asm("cvt.rna.tf32.f32 %0, %1;" : "=r"(r) : "f"(f));
    return r;
}

// ========== tf32 mma.sync GEMM core (R7 layout: [k][m], stride 136) ==========
#define SST  136
#define BUFU (16 * SST)

__device__ __forceinline__ void gemm_core(
    const float* __restrict__ A, const float* __restrict__ Wr,
    int M, int K,
    uint32_t* As, uint32_t* Ws,
    int arow, int r_st, int kqh, int mb, int nb, int gid, int tg,
    float (&acc)[2][8][4])
{
    const float4 z4 = make_float4(0.f, 0.f, 0.f, 0.f);
    float4 pa[2], pw[2];

#pragma unroll
    for (int i = 0; i < 2; i++) {
        int kb = (kqh + 2 * i) * 4;
        pa[i] = (arow < M) ? *(const float4*)(A + (size_t)arow * K + kb) : z4;
        pw[i] = *(const float4*)(Wr + kb);
    }
#pragma unroll
    for (int i = 0; i < 2; i++) {
        int kb = (kqh + 2 * i) * 4;
        As[(kb + 0) * SST + r_st] = cvt_tf32(pa[i].x);
        As[(kb + 1) * SST + r_st] = cvt_tf32(pa[i].y);
        As[(kb + 2) * SST + r_st] = cvt_tf32(pa[i].z);
        As[(kb + 3) * SST + r_st] = cvt_tf32(pa[i].w);
        Ws[(kb + 0) * SST + r_st] = cvt_tf32(pw[i].x);
        Ws[(kb + 1) * SST + r_st] = cvt_tf32(pw[i].y);
        Ws[(kb + 2) * SST + r_st] = cvt_tf32(pw[i].z);
        Ws[(kb + 3) * SST + r_st] = cvt_tf32(pw[i].w);
    }
    __syncthreads();

    const int nk = K >> 4;
    for (int t = 0; t < nk; t++) {
        const int cur = t & 1;
        if (t + 1 < nk) {
            const int k0 = (t + 1) << 4;
#pragma unroll
            for (int i = 0; i < 2; i++) {
                int kb = k0 + (kqh + 2 * i) * 4;
                pa[i] = (arow < M) ? *(const float4*)(A + (size_t)arow * K + kb) : z4;
                pw[i] = *(const float4*)(Wr + kb);
            }
        }
        const uint32_t* Ab = As + cur * BUFU;
        const uint32_t* Wb = Ws + cur * BUFU;
#pragma unroll
        for (int kk = 0; kk < 16; kk += 8) {
            uint32_t af[2][4], bf[8][2];
#pragma unroll
            for (int mt = 0; mt < 2; mt++) {
                int m = mb + mt * 16 + gid;
                af[mt][0] = Ab[(kk + tg)     * SST + m];
                af[mt][1] = Ab[(kk + tg)     * SST + m + 8];
                af[mt][2] = Ab[(kk + tg + 4) * SST + m];
                af[mt][3] = Ab[(kk + tg + 4) * SST + m + 8];
            }
#pragma unroll
            for (int nt = 0; nt < 8; nt++) {
                int n = nb + nt * 8 + gid;
                bf[nt][0] = Wb[(kk + tg)     * SST + n];
                bf[nt][1] = Wb[(kk + tg + 4) * SST + n];
            }
#pragma unroll
            for (int mt = 0; mt < 2; mt++)
#pragma unroll
                for (int nt = 0; nt < 8; nt++)
                    asm volatile(
                        "mma.sync.aligned.m16n8k8.row.col.f32.tf32.tf32.f32 "
                        "{%0,%1,%2,%3}, {%4,%5,%6,%7}, {%8,%9}, {%0,%1,%2,%3};"
                        : "+f"(acc[mt][nt][0]), "+f"(acc[mt][nt][1]),
                          "+f"(acc[mt][nt][2]), "+f"(acc[mt][nt][3])
                        : "r"(af[mt][0]), "r"(af[mt][1]), "r"(af[mt][2]), "r"(af[mt][3]),
                          "r"(bf[nt][0]), "r"(bf[nt][1]));
        }
        if (t + 1 < nk) {
            const int nxt = cur ^ 1;
            uint32_t* An = As + nxt * BUFU;
            uint32_t* Wn = Ws + nxt * BUFU;
#pragma unroll
            for (int i = 0; i < 2; i++) {
                int kb = (kqh + 2 * i) * 4;
                An[(kb + 0) * SST + r_st] = cvt_tf32(pa[i].x);
                An[(kb + 1) * SST + r_st] = cvt_tf32(pa[i].y);
                An[(kb + 2) * SST + r_st] = cvt_tf32(pa[i].z);
                An[(kb + 3) * SST + r_st] = cvt_tf32(pa[i].w);
                Wn[(kb + 0) * SST + r_st] = cvt_tf32(pw[i].x);
                Wn[(kb + 1) * SST + r_st] = cvt_tf32(pw[i].y);
                Wn[(kb + 2) * SST + r_st] = cvt_tf32(pw[i].z);
                Wn[(kb + 3) * SST + r_st] = cvt_tf32(pw[i].w);
            }
            __syncthreads();
        }
    }
}

#define GEMM_PREAMBLE                                        \
    __shared__ uint32_t As[2 * BUFU];                        \
    __shared__ uint32_t Ws[2 * BUFU];                        \
    const int tid  = threadIdx.x;                            \
    const int lane = tid & 31;                               \
    const int warp = tid >> 5;                               \
    const int gid  = lane >> 2;                              \
    const int tg   = lane & 3;                               \
    const int mb   = (warp & 3) * 32;                        \
    const int nb   = (warp >> 2) * 64;                       \
    const int bm   = blockIdx.y * 128;                       \
    const int r_st = tid & 127;                              \
    const int kqh  = tid >> 7;                               \
    const int arow = bm + r_st;                              \
    float acc[2][8][4];                                      \
    _Pragma("unroll")                                        \
    for (int a_ = 0; a_ < 2; a_++)                           \
        _Pragma("unroll")                                    \
        for (int b_ = 0; b_ < 8; b_++)                       \
            _Pragma("unroll")                                \
            for (int c_ = 0; c_ < 4; c_++) acc[a_][b_][c_] = 0.f;

// Standard GEMM: C[M,256] = A[M,K] @ W^T (+bias); W row stride = wstride,
// C row stride = cstride (floats).
__global__ __launch_bounds__(256) void mmagemm(const float* __restrict__ A,
                                               const float* __restrict__ W, int wstride,
                                               const float* __restrict__ bias,
                                               float* __restrict__ C, int cstride,
                                               int M, int K)
{
    GEMM_PREAMBLE
    const int bn = blockIdx.x * 128;
    const float* Wr = W + (size_t)(bn + r_st) * wstride;
    gemm_core(A, Wr, M, K, As, Ws, arow, r_st, kqh, mb, nb, gid, tg, acc);

#pragma unroll
    for (int mt = 0; mt < 2; mt++) {
        int row0 = bm + mb + mt * 16 + gid;
#pragma unroll
        for (int nt = 0; nt < 8; nt++) {
            int col = bn + nb + nt * 8 + tg * 2;
            float bx = 0.f, by = 0.f;
            if (bias) { bx = bias[col]; by = bias[col + 1]; }
            if (row0 < M)
                *(float2*)(C + (size_t)row0 * cstride + col) =
                    make_float2(acc[mt][nt][0] + bx, acc[mt][nt][1] + by);
            if (row0 + 8 < M)
                *(float2*)(C + (size_t)(row0 + 8) * cstride + col) =
                    make_float2(acc[mt][nt][2] + bx, acc[mt][nt][3] + by);
        }
    }
}

// Dual-output GEMM: reads A once, computes C1 = A@W1^T and C2 = A@W2^T.
__global__ __launch_bounds__(256) void mmagemm2(const float* __restrict__ A,
                                                const float* __restrict__ W1,
                                                const float* __restrict__ W2,
                                                float* __restrict__ C1,
                                                float* __restrict__ C2,
                                                int M, int K)
{
    GEMM_PREAMBLE
    const int bnf = blockIdx.x * 128;
    const float* W = (bnf < 256) ? W1 : W2;
    float* C = (bnf < 256) ? C1 : C2;
    const int bn = bnf & 255;
    const float* Wr = W + (size_t)(bn + r_st) * K;
    gemm_core(A, Wr, M, K, As, Ws, arow, r_st, kqh, mb, nb, gid, tg, acc);

#pragma unroll
    for (int mt = 0; mt < 2; mt++) {
        int row0 = bm + mb + mt * 16 + gid;
#pragma unroll
        for (int nt = 0; nt < 8; nt++) {
            int col = bn + nb + nt * 8 + tg * 2;
            if (row0 < M)
                *(float2*)(C + (size_t)row0 * 256 + col) =
                    make_float2(acc[mt][nt][0], acc[mt][nt][1]);
            if (row0 + 8 < M)
                *(float2*)(C + (size_t)(row0 + 8) * 256 + col) =
                    make_float2(acc[mt][nt][2], acc[mt][nt][3]);
        }
    }
}

// GEMM + node-gather epilogue: C[r,c] = acc + bias[c] + q[src[r],c] + q[dst[r],c].
// C row stride = cstride.
__global__ __launch_bounds__(256) void mmagemm_nodeadd(const float* __restrict__ A,
                                                       const float* __restrict__ W, int wstride,
                                                       const float* __restrict__ bias,
                                                       const float* __restrict__ q,
                                                       const int* __restrict__ srcIdx,
                                                       const int* __restrict__ dstIdx,
                                                       float* __restrict__ C, int cstride,
                                                       int M, int K)
{
    GEMM_PREAMBLE
    const int bn = blockIdx.x * 128;
    const float* Wr = W + (size_t)(bn + r_st) * wstride;
    gemm_core(A, Wr, M, K, As, Ws, arow, r_st, kqh, mb, nb, gid, tg, acc);

#pragma unroll
    for (int mt = 0; mt < 2; mt++) {
        int rbase = bm + mb + mt * 16 + gid;
#pragma unroll
        for (int half = 0; half < 2; half++) {
            int rr = rbase + half * 8;
            const float* qs = q + (size_t)srcIdx[rr] * 256;
            const float* qd = q + (size_t)dstIdx[rr] * 256;
#pragma unroll
            for (int nt = 0; nt < 8; nt++) {
                int col = bn + nb + nt * 8 + tg * 2;
                float v0 = acc[mt][nt][half * 2 + 0] + bias[col]     + qs[col]     + qd[col];
                float v1 = acc[mt][nt][half * 2 + 1] + bias[col + 1] + qs[col + 1] + qd[col + 1];
                *(float2*)(C + (size_t)rr * cstride + col) = make_float2(v0, v1);
            }
        }
    }
}

// GEMM + fused attention-score epilogue (P never stored). Requires M%128==0.
__global__ __launch_bounds__(256) void mmagemm_score(const float* __restrict__ A,
                                                     const float* __restrict__ W,
                                                     const float* __restrict__ ni,
                                                     const float* __restrict__ nj,
                                                     const int* __restrict__ srcIdx,
                                                     const int* __restrict__ dstIdx,
                                                     const float* __restrict__ attn,
                                                     const float* __restrict__ bias,
                                                     float* __restrict__ scoreOut,
                                                     float* __restrict__ maxOut,
                                                     int M, int K)
{
    GEMM_PREAMBLE
    const int bn = blockIdx.x * 128;
    const float* Wr = W + (size_t)(bn + r_st) * K;
    gemm_core(A, Wr, M, K, As, Ws, arow, r_st, kqh, mb, nb, gid, tg, acc);

    const int h = (bn + nb) >> 6;
#pragma unroll
    for (int mt = 0; mt < 2; mt++) {
        int rbase = bm + mb + mt * 16 + gid;
#pragma unroll
        for (int half = 0; half < 2; half++) {
            int rr = rbase + half * 8;
            int s_ = srcIdx[rr];
            int d_ = dstIdx[rr];
            const float* nip = ni + (size_t)s_ * 256;
            const float* njp = nj + (size_t)d_ * 256;
            float part = 0.f;
#pragma unroll
            for (int nt = 0; nt < 8; nt++) {
                int col = bn + nb + nt * 8 + tg * 2;
                float p0 = acc[mt][nt][half * 2 + 0];
                float p1 = acc[mt][nt][half * 2 + 1];
                part += lrelu(nip[col]     + njp[col]     + p0 + bias[col])     * attn[col];
                part += lrelu(nip[col + 1] + njp[col + 1] + p1 + bias[col + 1]) * attn[col + 1];
            }
            part += __shfl_xor_sync(0xffffffffu, part, 1);
            part += __shfl_xor_sync(0xffffffffu, part, 2);
            if (tg == 0) {
                scoreOut[(size_t)rr * 4 + h] = part;
                if (maxOut) atomicMaxF(&maxOut[(size_t)d_ * 4 + h], part);
            }
        }
    }
}

// ---------------- CSR build (3-stage scan) ----------------
__global__ void hist_kernel(const int* __restrict__ lgdst) {
    int e2 = blockIdx.x * blockDim.x + threadIdx.x;
    if (e2 < E2e) atomicAdd(&g_rcnt[lgdst[e2]], 1);
}

__global__ __launch_bounds__(256) void scan1_kernel() {
    __shared__ int sh[256];
    int j = blockIdx.x * 256 + threadIdx.x;
    int t = threadIdx.x;
    int v = (j < Ee) ? g_rcnt[j] : 0;
    sh[t] = v;
    __syncthreads();
    for (int off = 1; off < 256; off <<= 1) {
        int u = (t >= off) ? sh[t - off] : 0;
        __syncthreads();
        sh[t] += u;
        __syncthreads();
    }
    if (j < Ee) g_rowptr[j] = sh[t] - v;
    if (t == 255) g_bsum[blockIdx.x] = sh[255];
}

__global__ __launch_bounds__(1024) void scan2_kernel(int nblocks) {
    __shared__ int sh[1024];
    int t = threadIdx.x;
    int v = (t < nblocks) ? g_bsum[t] : 0;
    sh[t] = v;
    __syncthreads();
    for (int off = 1; off < 1024; off <<= 1) {
        int u = (t >= off) ? sh[t - off] : 0;
        __syncthreads();
        sh[t] += u;
        __syncthreads();
    }
    if (t < nblocks) g_boff[t] = sh[t] - v;
}

__global__ void scan3_kernel() {
    int j = blockIdx.x * 256 + threadIdx.x;
    if (j < Ee) g_rowptr[j] += g_boff[blockIdx.x];
    if (j == 0) g_rowptr[Ee] = E2e;
}

__global__ void scatter_csr_kernel(const int* __restrict__ lgdst) {
    int e2 = blockIdx.x * blockDim.x + threadIdx.x;
    if (e2 >= E2e) return;
    int d = lgdst[e2];
    int p = g_rowptr[d] + atomicAdd(&g_fill[d], 1);
    g_eidx[p] = e2;
}

// ---------------- small kernels ----------------
__global__ void fill_kernel(float* p, float v, int n) {
    int t = blockIdx.x * blockDim.x + threadIdx.x;
    if (t < n) p[t] = v;
}

__global__ __launch_bounds__(128) void agg_m1_kernel(const float* __restrict__ m_feats,
                                                     const float* __restrict__ x_feats) {
    int e = blockIdx.x;
    int c = threadIdx.x;
    int r0 = g_rowptr[e], r1 = g_rowptr[e + 1];
    float s = 0.f;
    for (int i = r0; i < r1; i++)
        s += x_feats[(size_t)g_eidx[i] * 128 + c];
    float inv = 1.f / fmaxf((float)(r1 - r0), 1.f);
    g_m1[(size_t)e * 256 + c]       = m_feats[(size_t)e * 128 + c];
    g_m1[(size_t)e * 256 + 128 + c] = s * inv;
}

// CSR segmented softmax stats per (dst l-node, head)
__global__ void lgsoftmax_kernel() {
    int t = blockIdx.x * blockDim.x + threadIdx.x;
    if (t >= Ee * 4) return;
    int e = t >> 2, h = t & 3;
    int r0 = g_rowptr[e], r1 = g_rowptr[e + 1];
    float m = -INFINITY;
    for (int i = r0; i < r1; i++)
        m = fmaxf(m, g_slg[(size_t)g_eidx[i] * 4 + h]);
    float den = 0.f;
    for (int i = r0; i < r1; i++)
        den += expf(g_slg[(size_t)g_eidx[i] * 4 + h] - m);
    g_maxlg[t] = m;
    g_denlg[t] = (r1 > r0) ? den : 1.f;
}

__global__ void g_exp_kernel(const int* __restrict__ dst) {
    int t = blockIdx.x * blockDim.x + threadIdx.x;
    if (t >= Ee * 4) return;
    int e = t >> 2, h = t & 3;
    int d = dst[e];
    float v = expf(g_sg[t] - g_maxg[(size_t)d * 4 + h]);
    g_sg[t] = v;
    atomicAdd(&g_deng[(size_t)d * 4 + h], v);
}

// fused CSR gather of both branches + softmax normalize + lrelu head-sum epilogue
__global__ __launch_bounds__(256) void gather_final_kernel(const int* __restrict__ lgsrc,
                                                           const int* __restrict__ gdst,
                                                           float* __restrict__ out) {
    __shared__ float red[256];
    int e = blockIdx.x;
    int c = threadIdx.x;
    int h = c >> 6;
    int r0 = g_rowptr[e], r1 = g_rowptr[e + 1];
    float agh = g_sg[(size_t)e * 4 + h] / g_deng[(size_t)gdst[e] * 4 + h];
    float mx  = g_maxlg[(size_t)e * 4 + h];
    float inv = 1.f / g_denlg[(size_t)e * 4 + h];
    float a1 = 0.f, a2 = 0.f;
    for (int i = r0; i < r1; i++) {
        int e2 = g_eidx[i];
        int s = lgsrc[e2];
        const float* hp = g_h12 + (size_t)s * 512;
        float alg = expf(g_slg[(size_t)e2 * 4 + h] - mx) * inv;
        a1 += hp[c]       * alg;
        a2 += hp[256 + c] * agh;
    }
    red[c] = lrelu(a1) + lrelu(a2);
    __syncthreads();
    if (c < 64)
        out[(size_t)e * 64 + c] = red[c] + red[c + 64] + red[c + 128] + red[c + 192];
}

// ---------------- host launch ----------------
extern "C" void kernel_launch(void* const* d_in, const int* in_sizes, int n_in,
                              void* d_out, int out_size)
{
    const float *l_feats = (const float*)d_in[0];
    const float *m_feats = (const float*)d_in[1];
    const float *x_feats = (const float*)d_in[2];
    const float *W_lg_node, *b_lg_node, *W_lg_ni, *W_lg_fij, *W_lg_nj, *lg_attn, *bias_lg;
    const float *W_g_node, *b_g_node, *W_g_ni, *W_g_fij, *W_g_nj, *g_attn, *bias_g;
    const int *gsrc, *gdst, *lgsrc, *lgdst;

    if (in_sizes[3] == Ee) {  // setup_inputs dict order
        gsrc = (const int*)d_in[3];  gdst = (const int*)d_in[4];
        lgsrc = (const int*)d_in[5]; lgdst = (const int*)d_in[6];
        W_lg_node = (const float*)d_in[7];  b_lg_node = (const float*)d_in[8];
        W_lg_ni   = (const float*)d_in[9];  W_lg_fij  = (const float*)d_in[10];
        W_lg_nj   = (const float*)d_in[11]; lg_attn   = (const float*)d_in[12];
        bias_lg   = (const float*)d_in[13];
        W_g_node  = (const float*)d_in[14]; b_g_node  = (const float*)d_in[15];
        W_g_ni    = (const float*)d_in[16]; W_g_fij   = (const float*)d_in[17];
        W_g_nj    = (const float*)d_in[18]; g_attn    = (const float*)d_in[19];
        bias_g    = (const float*)d_in[20];
    } else {                  // reference() signature order
        W_lg_node = (const float*)d_in[3];  b_lg_node = (const float*)d_in[4];
        W_lg_ni   = (const float*)d_in[5];  W_lg_fij  = (const float*)d_in[6];
        W_lg_nj   = (const float*)d_in[7];  lg_attn   = (const float*)d_in[8];
        bias_lg   = (const float*)d_in[9];
        W_g_node  = (const float*)d_in[10]; b_g_node  = (const float*)d_in[11];
        W_g_ni    = (const float*)d_in[12]; W_g_fij   = (const float*)d_in[13];
        W_g_nj    = (const float*)d_in[14]; g_attn    = (const float*)d_in[15];
        bias_g    = (const float*)d_in[16];
        gsrc  = (const int*)d_in[17]; gdst  = (const int*)d_in[18];
        lgsrc = (const int*)d_in[19]; lgdst = (const int*)d_in[20];
    }

    float *p_lg_ni, *p_lg_nj, *p_gni, *p_gnj, *p_q;
    float *p_m1, *p_h12, *p_maxg, *p_deng, *p_slg, *p_sg;
    int *p_rcnt, *p_fill;
    cudaGetSymbolAddress((void**)&p_lg_ni, g_lg_ni);
    cudaGetSymbolAddress((void**)&p_lg_nj, g_lg_nj);
    cudaGetSymbolAddress((void**)&p_gni,   g_gni);
    cudaGetSymbolAddress((void**)&p_gnj,   g_gnj);
    cudaGetSymbolAddress((void**)&p_q,     g_q);
    cudaGetSymbolAddress((void**)&p_m1,    g_m1);
    cudaGetSymbolAddress((void**)&p_h12,   g_h12);
    cudaGetSymbolAddress((void**)&p_maxg,  g_maxg);
    cudaGetSymbolAddress((void**)&p_deng,  g_deng);
    cudaGetSymbolAddress((void**)&p_slg,   g_slg);
    cudaGetSymbolAddress((void**)&p_sg,    g_sg);
    cudaGetSymbolAddress((void**)&p_rcnt,  g_rcnt);
    cudaGetSymbolAddress((void**)&p_fill,  g_fill);

    // ---- zero / init scratch (single stream, R11 order) ----
    cudaMemsetAsync(p_rcnt, 0, sizeof(int) * Ee, 0);
    cudaMemsetAsync(p_fill, 0, sizeof(int) * Ee, 0);
    cudaMemsetAsync(p_deng, 0, sizeof(float) * Nn * 4, 0);
    fill_kernel<<<(Nn * 4 + 255) / 256, 256>>>(p_maxg, -INFINITY, Nn * 4);

    // ---- CSR build (3-stage scan) ----
    const int nsb = (Ee + 255) / 256;   // 625
    hist_kernel<<<(E2e + 255) / 256, 256>>>(lgdst);
    scan1_kernel<<<nsb, 256>>>();
    scan2_kernel<<<1, 1024>>>(nsb);
    scan3_kernel<<<nsb, 256>>>();
    scatter_csr_kernel<<<(E2e + 255) / 256, 256>>>(lgdst);

    // ---- projection GEMMs (dual-output: one A read each) ----
    dim3 blk(256);
    const int gE  = (Ee  + 127) / 128;
    const int gE2 = (E2e + 127) / 128;
    const int gN  = (Nn  + 127) / 128;
    mmagemm2<<<dim3(4, gE), blk>>>(m_feats, W_lg_ni, W_lg_nj, p_lg_ni, p_lg_nj, Ee, 128);
    mmagemm2<<<dim3(4, gN), blk>>>(l_feats, W_g_ni,  W_g_nj,  p_gni,   p_gnj,   Nn, 128);

    // ---- fij GEMMs fused with attention scores (no fij materialization) ----
    mmagemm_score<<<dim3(2, gE2), blk>>>(x_feats, W_lg_fij, p_lg_ni, p_lg_nj,
                                         lgsrc, lgdst, lg_attn, bias_lg,
                                         p_slg, nullptr, E2e, 128);
    mmagemm_score<<<dim3(2, gE), blk>>>(m_feats, W_g_fij, p_gni, p_gnj,
                                        gsrc, gdst, g_attn, bias_g,
                                        p_sg, p_maxg, Ee, 128);

    // ---- h1: m1 = [m_feats, mean-agg(x)] then K=256 GEMM -> h12[:,0:256] ----
    agg_m1_kernel<<<Ee, 128>>>(m_feats, x_feats);
    mmagemm<<<dim3(2, gE), blk>>>(p_m1, W_lg_node, 256, b_lg_node, p_h12, 512, Ee, 256);

    // ---- h2 via q-trick -> h12[:,256:512] ----
    mmagemm<<<dim3(2, gN), blk>>>(l_feats, W_g_node, 256, nullptr, p_q, 256, Nn, 128);
    mmagemm_nodeadd<<<dim3(2, gE), blk>>>(m_feats, W_g_node + 128, 256, b_g_node,
                                          p_q, gsrc, gdst, p_h12 + 256, 512, Ee, 128);

    // ---- softmax stats ----
    lgsoftmax_kernel<<<(Ee * 4 + 255) / 256, 256>>>();
    g_exp_kernel<<<(Ee * 4 + 255) / 256, 256>>>(gdst);

    // ---- fused gather + normalize + epilogue ----
    gather_final_kernel<<<Ee, 256>>>(lgsrc, gdst, (float*)d_out);
}